// round 1
// baseline (speedup 1.0000x reference)
#include <cuda_runtime.h>
#include <cstdint>

#define NIMG 8
#define AN   16384
#define CN   21
#define NCLS 20
#define TOPK 100
#define NB   564          // buckets for scores in (0.05, 1): (bits>>16) in [0x3D4C, 0x3F7F]
#define BBASE 0x3D4Cu
#define THR_PROB 0.05f
#define THR_NMS  0.45f

// -------- device scratch (no allocations allowed) --------
__device__ float  g_scores[NIMG * NCLS * AN];   // thresholded per-class scores, -1 if inactive
__device__ float4 g_boxes [NIMG * AN];          // decoded clipped corner boxes
__device__ float  g_rows  [NIMG * NCLS * TOPK * 6];
__device__ int    g_counts[NIMG * NCLS];

// ---------------- stage 1: softmax + decode ----------------
__global__ void __launch_bounds__(256) k_prep(const float* __restrict__ cls,
                                              const float* __restrict__ reg,
                                              const float* __restrict__ anc) {
    int t = blockIdx.x * blockDim.x + threadIdx.x;
    if (t >= NIMG * AN) return;
    int a = t & (AN - 1);
    int n = t >> 14;

    const float* cp = cls + (size_t)t * CN;
    float x[CN];
    #pragma unroll
    for (int i = 0; i < CN; i++) x[i] = cp[i];
    float mx = x[0];
    #pragma unroll
    for (int i = 1; i < CN; i++) mx = fmaxf(mx, x[i]);
    float e[CN];
    float sum = 0.f;
    #pragma unroll
    for (int i = 0; i < CN; i++) { e[i] = expf(x[i] - mx); sum += e[i]; }
    #pragma unroll
    for (int c = 1; c < CN; c++) {
        float p = __fdiv_rn(e[c], sum);
        g_scores[(size_t)(n * NCLS + (c - 1)) * AN + a] = (p > THR_PROB) ? p : -1.0f;
    }

    float4 l   = ((const float4*)reg)[t];
    float4 an4 = ((const float4*)anc)[a];
    float cx = an4.x + l.x * 0.1f * an4.z;
    float cy = an4.y + l.y * 0.1f * an4.w;
    float w  = an4.z * expf(l.z * 0.2f);
    float h  = an4.w * expf(l.w * 0.2f);
    float hx = w * 0.5f, hy = h * 0.5f;
    float x1 = fminf(fmaxf(cx - hx, 0.f), 1.f);
    float y1 = fminf(fmaxf(cy - hy, 0.f), 1.f);
    float x2 = fminf(fmaxf(cx + hx, 0.f), 1.f);
    float y2 = fminf(fmaxf(cy + hy, 0.f), 1.f);
    g_boxes[t] = make_float4(x1, y1, x2, y2);
}

__device__ __forceinline__ bool iou_gt(float4 p, float4 q) {
    float areaP = (p.z - p.x) * (p.w - p.y);
    float areaQ = (q.z - q.x) * (q.w - q.y);
    float ltx = fmaxf(p.x, q.x), lty = fmaxf(p.y, q.y);
    float rbx = fminf(p.z, q.z), rby = fminf(p.w, q.w);
    float iw = fmaxf(rbx - ltx, 0.f), ih = fmaxf(rby - lty, 0.f);
    float inter = iw * ih;
    float uni = areaP + areaQ - inter;
    float iou = (uni > 0.f) ? __fdiv_rn(inter, uni) : 0.f;
    return iou > THR_NMS;
}

// ---------------- stage 2: per-(image,class) sorted-greedy NMS ----------------
// Dynamic smem: keys[AN] u32 | hist[576] | off[576] | cur[576] | selB[100] float4
#define SMEM_NMS ((AN + 3 * 576) * 4 + TOPK * 16)

__global__ void __launch_bounds__(256) k_nms() {
    extern __shared__ uint32_t sm[];
    uint32_t* keys = sm;
    uint32_t* hist = sm + AN;
    uint32_t* off  = hist + 576;
    uint32_t* cur  = off + 576;
    float4*   selB = (float4*)(cur + 576);

    __shared__ int    s_selcnt, s_done;
    __shared__ float4 s_cbox[8];
    __shared__ float  s_cscore[8];
    __shared__ int    s_csupp[8], s_cvalid[8];

    const int tid  = threadIdx.x;
    const int wid  = tid >> 5, lane = tid & 31;
    const int n    = blockIdx.x / NCLS;
    const int cc   = blockIdx.x % NCLS;           // class = cc+1
    const float*  sc   = g_scores + (size_t)(n * NCLS + cc) * AN;
    const float4* boxN = g_boxes + (size_t)n * AN;
    float* rowBase = g_rows + (size_t)(n * NCLS + cc) * TOPK * 6;

    for (int i = tid; i < 576; i += 256) hist[i] = 0;
    if (tid == 0) { s_selcnt = 0; s_done = 0; }
    __syncthreads();

    // histogram
    for (int a = tid; a < AN; a += 256) {
        float s = sc[a];
        if (s > 0.f) atomicAdd(&hist[(__float_as_uint(s) >> 16) - BBASE], 1u);
    }
    __syncthreads();

    // exclusive scan over 576 buckets (warp 0, 18 per lane)
    if (tid < 32) {
        uint32_t sum = 0;
        #pragma unroll
        for (int i = 0; i < 18; i++) sum += hist[lane * 18 + i];
        uint32_t pre = sum;
        #pragma unroll
        for (int d = 1; d < 32; d <<= 1) {
            uint32_t v = __shfl_up_sync(0xFFFFFFFFu, pre, d);
            if (lane >= d) pre += v;
        }
        uint32_t run = pre - sum;
        #pragma unroll
        for (int i = 0; i < 18; i++) {
            uint32_t hv = hist[lane * 18 + i];
            off[lane * 18 + i] = run;
            cur[lane * 18 + i] = run;
            run += hv;
        }
    }
    __syncthreads();

    // scatter: key packs low-16 score bits + (16383 - anchor) for exact tie-break
    for (int a = tid; a < AN; a += 256) {
        float s = sc[a];
        if (s > 0.f) {
            uint32_t bits = __float_as_uint(s);
            uint32_t pos  = atomicAdd(&cur[(bits >> 16) - BBASE], 1u);
            keys[pos] = ((bits & 0xFFFFu) << 14) | (uint32_t)(16383 - a);
        }
    }
    __syncthreads();

    // greedy NMS, buckets high->low; lazy suppression against selected list
    for (int bk = NB - 1; bk >= 0; bk--) {
        if (s_done) break;
        uint32_t lo  = off[bk];
        uint32_t cnt = cur[bk] - lo;
        if (cnt == 0) continue;

        if (cnt > 1) {
            if (cnt <= 32) {
                if (wid == 0) {
                    uint32_t v = (lane < (int)cnt) ? keys[lo + lane] : 0u;
                    #pragma unroll
                    for (uint32_t k = 2; k <= 32; k <<= 1)
                        #pragma unroll
                        for (uint32_t j = k >> 1; j > 0; j >>= 1) {
                            uint32_t o = __shfl_xor_sync(0xFFFFFFFFu, v, j);
                            bool keepMin = (((uint32_t)lane & j) == 0) == (((uint32_t)lane & k) != 0);
                            uint32_t mn = v < o ? v : o;
                            uint32_t mx2 = v < o ? o : v;
                            v = keepMin ? mn : mx2;   // descending overall
                        }
                    if (lane < (int)cnt) keys[lo + lane] = v;
                }
                __syncthreads();
            } else {
                for (uint32_t ph = 0; ph < cnt; ph++) {  // odd-even transposition (rare path)
                    for (uint32_t p = tid; 2 * p + (ph & 1) + 1 < cnt; p += 256) {
                        uint32_t i0 = lo + 2 * p + (ph & 1);
                        uint32_t xv = keys[i0], yv = keys[i0 + 1];
                        if (xv < yv) { keys[i0] = yv; keys[i0 + 1] = xv; }
                    }
                    __syncthreads();
                }
            }
        }

        // batches of 8 candidates, one warp each
        for (uint32_t t0 = 0; t0 < cnt; t0 += 8) {
            int snap = s_selcnt;
            int i = (int)t0 + wid;
            bool valid = i < (int)cnt;
            if (valid) {
                uint32_t key = keys[lo + i];
                uint32_t a = 16383u - (key & 0x3FFFu);
                float4 cb = boxN[a];
                bool sup = false;
                for (int j = lane; j < snap; j += 32)
                    if (iou_gt(selB[j], cb)) { sup = true; break; }
                sup = __any_sync(0xFFFFFFFFu, sup);
                if (lane == 0) {
                    s_cbox[wid] = cb;
                    s_cscore[wid] = __uint_as_float((((uint32_t)bk + BBASE) << 16) | ((key >> 14) & 0xFFFFu));
                    s_csupp[wid] = sup ? 1 : 0;
                    s_cvalid[wid] = 1;
                }
            } else if (lane == 0) {
                s_cvalid[wid] = 0;
            }
            __syncthreads();
            if (tid == 0) {
                int c2 = s_selcnt;
                for (int w2 = 0; w2 < 8 && c2 < TOPK; w2++) {
                    if (!s_cvalid[w2] || s_csupp[w2]) continue;
                    float4 cb = s_cbox[w2];
                    bool ok = true;
                    for (int j = snap; j < c2; j++)
                        if (iou_gt(selB[j], cb)) { ok = false; break; }
                    if (!ok) continue;
                    selB[c2] = cb;
                    float* r = rowBase + c2 * 6;
                    r[0] = cb.x; r[1] = cb.y; r[2] = cb.z; r[3] = cb.w;
                    r[4] = s_cscore[w2]; r[5] = (float)(cc + 1);
                    c2++;
                }
                s_selcnt = c2;
                if (c2 >= TOPK) s_done = 1;
            }
            __syncthreads();
            if (s_done) break;
        }
    }
    __syncthreads();
    if (tid == 0) g_counts[n * NCLS + cc] = s_selcnt;
}

// ---------------- stage 3: per-image top-100 (lax.top_k semantics) ----------------
__global__ void __launch_bounds__(256) k_topk(float* __restrict__ out) {
    __shared__ uint64_t kb[2048];
    const int n = blockIdx.x, tid = threadIdx.x;

    for (int e = tid; e < 2048; e += 256) {
        uint64_t key = 0ull;
        if (e < NCLS * TOPK) {
            int c = e / TOPK, k = e % TOPK;
            if (k < g_counts[n * NCLS + c]) {
                float s = g_rows[(((size_t)(n * NCLS + c)) * TOPK + k) * 6 + 4];
                uint32_t flat = (uint32_t)((c + 1) * TOPK + k);   // flat idx in [N, C*TOPK] layout
                key = ((uint64_t)__float_as_uint(s) << 32) | (uint64_t)(4095u - flat);
            }
        }
        kb[e] = key;
    }
    __syncthreads();

    for (int k = 2; k <= 2048; k <<= 1)
        for (int j = k >> 1; j > 0; j >>= 1) {
            for (int i = tid; i < 1024; i += 256) {
                int pos = ((i & ~(j - 1)) << 1) | (i & (j - 1));
                int par = pos | j;
                uint64_t xv = kb[pos], yv = kb[par];
                bool desc = ((pos & k) == 0);
                if (desc ? (xv < yv) : (xv > yv)) { kb[pos] = yv; kb[par] = xv; }
            }
            __syncthreads();
        }

    if (tid < TOPK) {
        uint64_t key = kb[tid];
        float* o = out + ((size_t)n * TOPK + tid) * 6;
        if ((key >> 32) != 0ull) {
            uint32_t flat = 4095u - (uint32_t)key;
            int c = (int)(flat / TOPK) - 1;
            int k = (int)(flat % TOPK);
            const float* r = g_rows + (((size_t)(n * NCLS + c)) * TOPK + k) * 6;
            #pragma unroll
            for (int j = 0; j < 6; j++) o[j] = r[j];
        } else {
            #pragma unroll
            for (int j = 0; j < 6; j++) o[j] = 0.f;
        }
    }
}

extern "C" void kernel_launch(void* const* d_in, const int* in_sizes, int n_in,
                              void* d_out, int out_size) {
    (void)in_sizes; (void)n_in; (void)out_size;
    const float* cls = (const float*)d_in[0];
    const float* reg = (const float*)d_in[1];
    const float* anc = (const float*)d_in[2];
    float* out = (float*)d_out;

    cudaFuncSetAttribute(k_nms, cudaFuncAttributeMaxDynamicSharedMemorySize, SMEM_NMS);

    k_prep<<<(NIMG * AN) / 256, 256>>>(cls, reg, anc);
    k_nms <<<NIMG * NCLS, 256, SMEM_NMS>>>();
    k_topk<<<NIMG, 256>>>(out);
}